// round 8
// baseline (speedup 1.0000x reference)
#include <cuda_runtime.h>
#include <math.h>

#define Bsz 128
#define Tt  256
#define Hd  1024
#define BT  (Bsz * Tt)
#define BH  (Bsz * Hd)

// Scratch (device globals: sanctioned alloc-free workaround)
__device__ __align__(16) unsigned g_xfrag[(size_t)BT * Hd]; // x as mma-fragment tf32 per token (128 MiB)
__device__ __align__(16) float g_h0f[BH];                   // final h0 (fp32, for finalize)
__device__ __align__(16) float g_partA[2][BH];              // Gh0 partials (kh 0/1)
__device__ __align__(16) float g_partB[4][BH];              // Gi1 kh0/1, Gh1 kh0/1
__device__ __align__(16) float g_ringP[4][2][BH];           // Gp partial ring, depth 4, per kh
__device__ __align__(16) unsigned g_h0frag[4][BH];          // h0 fragment layout, depth-4 ring
__device__ __align__(16) unsigned g_h1frag[2][BH];          // h1 fragment layout, parity
__device__ int g_cntA[16], g_cntB[16];                      // tile combine counters (monotonic)
__device__ int g_barA, g_barB, g_barP;                      // group phase barriers (monotonic)

// ---------------------------------------------------------------------------
// helpers
// ---------------------------------------------------------------------------
__device__ __forceinline__ unsigned f2tf(float x) {
    unsigned u;
    asm("cvt.rna.tf32.f32 %0, %1;" : "=r"(u) : "f"(x));
    return u;
}

__device__ __forceinline__ int ld_acq(const int* a) {
    int v;
    asm volatile("ld.acquire.gpu.s32 %0, [%1];" : "=r"(v) : "l"(a) : "memory");
    return v;
}

__device__ __forceinline__ void red_release(int* a) {
    asm volatile("red.release.gpu.global.add.s32 [%0], 1;" :: "l"(a) : "memory");
}

__device__ __forceinline__ void wait_ge(const int* a, int tgt) {
    if (ld_acq(a) >= tgt) return;
    while (ld_acq(a) < tgt) __nanosleep(32);
}

#define MMA_TF32(C, A, B)                                                     \
    asm volatile(                                                             \
        "mma.sync.aligned.m16n8k8.row.col.f32.tf32.tf32.f32 "                 \
        "{%0,%1,%2,%3}, {%4,%5,%6,%7}, {%8,%9}, {%0,%1,%2,%3};"               \
        : "+f"((C)[0]), "+f"((C)[1]), "+f"((C)[2]), "+f"((C)[3])              \
        : "r"((A).x), "r"((A).y), "r"((A).z), "r"((A).w),                     \
          "r"((B).x), "r"((B).y))

// Fragment index of element (row b in 0..127, col n in 0..1023), m16n8k8 A layout:
// uint index = ((k8*8 + mtile)*32 + lane)*4 + reg
__device__ __forceinline__ int frag_idx(int b, int n) {
    int kc = n & 7;
    int lane = (b & 7) * 4 + (kc & 3);
    int reg  = ((b >> 3) & 1) + ((kc >> 2) << 1);
    return ((((n >> 3) << 3) + (b >> 4)) * 32 + lane) * 4 + reg;
}

// ---------------------------------------------------------------------------
// Init: zero sync state, fill initial-state fragment buffers.
// h0frag ring slot 3 <- layer0 init (A(0) reads (0-1)&3 = 3);
// h1frag[1] <- layer1 init (Gh1(1) reads p&1 = 1).
// ---------------------------------------------------------------------------
__global__ void init_kernel(const float* __restrict__ h0in)
{
    int idx = blockIdx.x * blockDim.x + threadIdx.x;
    if (idx < 16) { g_cntA[idx] = 0; g_cntB[idx] = 0; }
    if (idx == 16) { g_barA = 0; g_barB = 0; g_barP = 0; }
    for (int e = idx; e < 2 * BH; e += gridDim.x * blockDim.x) {
        int which = e >> 17;
        int r = e & (BH - 1);
        int b = r >> 10, n = r & 1023;
        unsigned v = f2tf(h0in[which * Hd + n]);
        if (which == 0) g_h0frag[3][frag_idx(b, n)] = v;
        else            g_h1frag[1][frag_idx(b, n)] = v;
    }
}

// ---------------------------------------------------------------------------
// xprep: x [B,T,H] fp32 -> per-token fragment tf32 in g_xfrag (one-shot).
// ---------------------------------------------------------------------------
__global__ void xprep_kernel(const float* __restrict__ x)
{
    const int total = BT * Hd / 4;
    for (int e = blockIdx.x * blockDim.x + threadIdx.x; e < total;
         e += gridDim.x * blockDim.x) {
        int n  = (e & 255) * 4;
        int bt = e >> 8;
        int b  = bt >> 8;
        int t  = bt & 255;
        float4 v = *(const float4*)(x + (size_t)e * 4);
        unsigned* dst = g_xfrag + (size_t)t * BH;
        dst[frag_idx(b, n + 0)] = f2tf(v.x);
        dst[frag_idx(b, n + 1)] = f2tf(v.y);
        dst[frag_idx(b, n + 2)] = f2tf(v.z);
        dst[frag_idx(b, n + 3)] = f2tf(v.w);
    }
}

// ---------------------------------------------------------------------------
// Persistent kernel. 128 blocks x 512 threads, 1 block/SM.
//   part = bid/32: 0=Gh0 [A-critical], 1=Gi1 [B], 2=Gh1 [B], 3=Gp [ring-ahead]
//   sub = bid%32: tile = sub>>1 (N-tile of 64), kh = sub&1 (K-half of 512).
// Weights: 128KB fragment-ready smem, loaded once. A operands: smem-staged
// in 2x32KB double-buffered chunks (each block reads its slice ONCE from L2).
// Sync: monotonic counters, red.release arrivals, ld.acquire polls, no fences.
//   Gh0(p): entry barA>=32p; combine cntA>=2(p+1), barP>=32(p+1),
//           WAR barB>=64(p-3); epilogue -> h0frag[p&3]; arrive barA.
//   Gp(p):  entry barA>=32(p-3) (ring slot free); partial->ringP[p&3]; arrive barP.
//   B(p):   entry barA>=32p, barB>=64(p-1); combine cntB>=4p;
//           epilogue -> out[:,p-1,:], h1frag[(p-1)&1]; arrive barB.
// ---------------------------------------------------------------------------
extern __shared__ unsigned smemAll[];   // Bw: 32768 uints (128KB) + As: 2x8192 (64KB)

__global__ __launch_bounds__(512, 1) void persistent_kernel(
    const float* __restrict__ Wi, const float* __restrict__ bi,
    const float* __restrict__ Wh, const float* __restrict__ bh,
    float* __restrict__ out)
{
    const int part = blockIdx.x >> 5;     // 0..3
    const int sub  = blockIdx.x & 31;
    const int tile = sub >> 1;
    const int kh   = sub & 1;

    const int tid  = threadIdx.x;
    const int lane = tid & 31;
    const int wid  = tid >> 5;
    const int wm   = wid & 7;             // M-tile (16 rows)
    const int wn   = wid >> 3;            // N-group (32 cols)
    const int n0   = tile * 64;
    const int kstart = kh * 512;

    unsigned* Bw = smemAll;               // [64 k8][8 ntile][32 lane][2 reg]
    unsigned* As = smemAll + 32768;       // [2 buf][8 k8][8 mt][32 lane][4 reg]

    const float* wbase = (part == 0) ? Wh
                       : (part == 1) ? Wi + (size_t)Hd * Hd
                       : (part == 2) ? Wh + (size_t)Hd * Hd
                                     : Wi;

    // ---- one-time weight preload into fragment-ready smem ----
#pragma unroll 4
    for (int i = 0; i < 16; i++) {
        int idx = tid + 512 * i;
        int krow = idx >> 4;
        int c4   = idx & 15;
        float4 w = *(const float4*)(wbase + (size_t)(kstart + krow) * Hd + n0 + c4 * 4);
        int k8 = krow >> 3, kk = krow & 7, ntile = c4 >> 1;
        int base = ((k8 * 8 + ntile) * 32 + (c4 & 1) * 16 + (kk & 3)) * 2 + (kk >> 2);
        Bw[base +  0] = f2tf(w.x);
        Bw[base +  8] = f2tf(w.y);
        Bw[base + 16] = f2tf(w.z);
        Bw[base + 24] = f2tf(w.w);
    }
    __syncthreads();

    float* mp0 = (part == 0) ? g_partA[kh]
               : (part == 1) ? g_partB[kh]
               : (part == 2) ? g_partB[2 + kh] : (float*)0;

    const bool isB = (part == 1 || part == 2);
    const int pstart = isB ? 1 : 0;
    const int pend   = isB ? Tt : Tt - 1;

    for (int p = pstart; p <= pend; ++p) {
        // ---- entry flow wait ----
        if (tid == 0) {
            if (part == 0) {
                if (p > 0) wait_ge(&g_barA, 32 * p);
            } else if (part == 3) {
                if (p >= 4) wait_ge(&g_barA, 32 * (p - 3));
            } else {
                wait_ge(&g_barA, 32 * p);
                if (p >= 2) wait_ge(&g_barB, 64 * (p - 1));
            }
        }
        __syncthreads();

        const unsigned* afrag =
            (part == 2) ? g_h1frag[p & 1] :
            (part == 3) ? (g_xfrag + (size_t)p * BH)
                        : g_h0frag[(p - 1) & 3];
        const uint4* src4 = (const uint4*)afrag + (size_t)kh * 16384; // kh*64 k8 * 256 u4

        float c[4][4];
#pragma unroll
        for (int nt = 0; nt < 4; nt++)
#pragma unroll
            for (int r = 0; r < 4; r++) c[nt][r] = 0.0f;

        // ---- stage chunk 0 ----
        {
            uint4* d = (uint4*)As;
#pragma unroll
            for (int j = 0; j < 4; j++)
                d[tid + j * 512] = __ldcg(src4 + tid + j * 512);
        }
        __syncthreads();

        int buf = 0;
#pragma unroll
        for (int ck = 0; ck < 8; ck++) {
            if (ck < 7) {
                const uint4* s = src4 + (ck + 1) * 2048;
                uint4* d = (uint4*)As + (buf ^ 1) * 2048;
#pragma unroll
                for (int j = 0; j < 4; j++)
                    d[tid + j * 512] = __ldcg(s + tid + j * 512);
            }
            const uint4* Af = (const uint4*)As + buf * 2048;
#pragma unroll
            for (int k8l = 0; k8l < 8; k8l++) {
                uint4 a = Af[(k8l * 8 + wm) * 32 + lane];
                uint2 bfr[4];
#pragma unroll
                for (int nt = 0; nt < 4; nt++)
                    bfr[nt] = *(const uint2*)&Bw[((((ck * 8 + k8l) << 3) + wn * 4 + nt) * 32 + lane) * 2];
#pragma unroll
                for (int nt = 0; nt < 4; nt++)
                    MMA_TF32(c[nt], a, bfr[nt]);
            }
            __syncthreads();
            buf ^= 1;
        }

        // ---- partial -> global ----
        {
            float* mp = (part == 3) ? g_ringP[p & 3][kh] : mp0;
            const int gq = lane >> 2, tq = lane & 3;
#pragma unroll
            for (int nt = 0; nt < 4; nt++) {
                int row = wm * 16 + gq;
                int col = n0 + wn * 32 + nt * 8 + 2 * tq;
                *(float2*)&mp[(size_t)row * Hd + col] = make_float2(c[nt][0], c[nt][1]);
                *(float2*)&mp[(size_t)(row + 8) * Hd + col] = make_float2(c[nt][2], c[nt][3]);
            }
        }
        __syncthreads();

        if (part == 3) {                 // Gp: publish ring partial, done
            if (tid == 0) red_release(&g_barP);
            continue;
        }

        // ---- combine wait ----
        if (tid == 0) {
            if (part == 0) {
                red_release(&g_cntA[tile]);
                wait_ge(&g_cntA[tile], 2 * (p + 1));
                wait_ge(&g_barP, 32 * (p + 1));
                if (p >= 4) wait_ge(&g_barB, 64 * (p - 3));   // WAR on h0frag slot p&3
            } else {
                red_release(&g_cntB[tile]);
                wait_ge(&g_cntB[tile], 4 * p);
            }
        }
        __syncthreads();

        // ---- distributed epilogue ----
        if (part == 0) {
            // 2 blocks/tile: kh selects 64-row half; 2 float4 per thread
            const int row = kh * 64 + (tid >> 3);
            const int nb  = n0 + (tid & 7) * 8;
            unsigned* dstf = g_h0frag[p & 3];
            const float* rp0 = g_ringP[p & 3][0];
            const float* rp1 = g_ringP[p & 3][1];
#pragma unroll
            for (int v = 0; v < 8; v += 4) {
                const int n = nb + v;
                float4 a = __ldcg((const float4*)&g_partA[0][(size_t)row * Hd + n]);
                float4 b = __ldcg((const float4*)&g_partA[1][(size_t)row * Hd + n]);
                float4 q = __ldcg((const float4*)&rp0[(size_t)row * Hd + n]);
                float4 s = __ldcg((const float4*)&rp1[(size_t)row * Hd + n]);
                float4 b1 = *(const float4*)&bi[n];
                float4 b2 = *(const float4*)&bh[n];
                float r0 = tanhf(a.x + b.x + q.x + s.x + b1.x + b2.x);
                float r1 = tanhf(a.y + b.y + q.y + s.y + b1.y + b2.y);
                float r2 = tanhf(a.z + b.z + q.z + s.z + b1.z + b2.z);
                float r3 = tanhf(a.w + b.w + q.w + s.w + b1.w + b2.w);
                if (p == Tt - 1)
                    *(float4*)&g_h0f[(size_t)row * Hd + n] = make_float4(r0, r1, r2, r3);
                dstf[frag_idx(row, n + 0)] = f2tf(r0);
                dstf[frag_idx(row, n + 1)] = f2tf(r1);
                dstf[frag_idx(row, n + 2)] = f2tf(r2);
                dstf[frag_idx(row, n + 3)] = f2tf(r3);
            }
        } else {
            // 4 blocks/tile: chunk of 32 rows; 1 float4 per thread
            const int chunk = (part - 1) * 2 + kh;
            const int row = chunk * 32 + (tid >> 4);
            const int n   = n0 + (tid & 15) * 4;
            const int tt  = p - 1;
            unsigned* dstf = g_h1frag[(p - 1) & 1];
            float4 s2 = __ldcg((const float4*)&g_partB[0][(size_t)row * Hd + n]);
            float4 s3 = __ldcg((const float4*)&g_partB[1][(size_t)row * Hd + n]);
            float4 s4 = __ldcg((const float4*)&g_partB[2][(size_t)row * Hd + n]);
            float4 s5 = __ldcg((const float4*)&g_partB[3][(size_t)row * Hd + n]);
            float4 b1 = *(const float4*)&bi[Hd + n];
            float4 b2 = *(const float4*)&bh[Hd + n];
            float r0 = tanhf(s2.x + s3.x + s4.x + s5.x + b1.x + b2.x);
            float r1 = tanhf(s2.y + s3.y + s4.y + s5.y + b1.y + b2.y);
            float r2 = tanhf(s2.z + s3.z + s4.z + s5.z + b1.z + b2.z);
            float r3 = tanhf(s2.w + s3.w + s4.w + s5.w + b1.w + b2.w);
            *(float4*)&out[((size_t)row * Tt + tt) * Hd + n] = make_float4(r0, r1, r2, r3);
            dstf[frag_idx(row, n + 0)] = f2tf(r0);
            dstf[frag_idx(row, n + 1)] = f2tf(r1);
            dstf[frag_idx(row, n + 2)] = f2tf(r2);
            dstf[frag_idx(row, n + 3)] = f2tf(r3);
        }

        // ---- group phase arrival ----
        __syncthreads();
        if (tid == 0) red_release((part == 0) ? &g_barA : &g_barB);
    }
}

// ---------------------------------------------------------------------------
// Finalize: h_n[b][0] = h0_{T-1}, h_n[b][1] = h1_{T-1} (= out[:,T-1,:])
// ---------------------------------------------------------------------------
__global__ void finalize_kernel(float* __restrict__ out)
{
    int idx = blockIdx.x * blockDim.x + threadIdx.x;
    if (idx >= BH) return;
    int b = idx / Hd, h = idx % Hd;
    float* hn = out + (size_t)BT * Hd;
    hn[((size_t)b * 2 + 0) * Hd + h] = g_h0f[(size_t)b * Hd + h];
    hn[((size_t)b * 2 + 1) * Hd + h] = out[((size_t)b * Tt + (Tt - 1)) * Hd + h];
}

// ---------------------------------------------------------------------------
extern "C" void kernel_launch(void* const* d_in, const int* in_sizes, int n_in,
                              void* d_out, int out_size)
{
    const float* x    = (const float*)d_in[0];   // [B,T,H]
    const float* h0in = (const float*)d_in[1];   // [1,L,H]
    const float* Wi   = (const float*)d_in[2];   // [L,H,H]
    const float* bi   = (const float*)d_in[3];   // [L,H]
    const float* Wh   = (const float*)d_in[4];   // [L,H,H]
    const float* bh   = (const float*)d_in[5];   // [L,H]
    float* out = (float*)d_out;                  // [B,T,H] then [B,L,H]

    init_kernel<<<256, 256>>>(h0in);
    xprep_kernel<<<8192, 256>>>(x);

    cudaFuncSetAttribute(persistent_kernel,
                         cudaFuncAttributeMaxDynamicSharedMemorySize, 196608);
    persistent_kernel<<<128, 512, 196608>>>(Wi, bi, Wh, bh, out);

    finalize_kernel<<<(BH + 255) / 256, 256>>>(out);
}

// round 9
// speedup vs baseline: 2.2048x; 2.2048x over previous
#include <cuda_runtime.h>
#include <math.h>

#define Bsz 128
#define Tt  256
#define Hd  1024
#define BT  (Bsz * Tt)
#define BH  (Bsz * Hd)

// Scratch (device globals: sanctioned alloc-free workaround)
__device__ __align__(16) unsigned g_xfrag[(size_t)BT * Hd]; // x as mma-fragment tf32 per token (128 MiB)
__device__ __align__(16) float g_h0f[BH];                   // final h0 (fp32, for finalize)
__device__ __align__(16) float g_part[8][BH];               // per-phase GEMM partials
__device__ __align__(16) unsigned g_h0frag[2][BH];          // h0 fragment layout, parity buffers
__device__ __align__(16) unsigned g_h1frag[2][BH];          // h1 fragment layout, parity buffers
__device__ int g_cntA[16], g_cntB[16];                      // tile combine counters (monotonic)
__device__ int g_barA, g_barB;                              // group phase barriers (monotonic)

// ---------------------------------------------------------------------------
// helpers
// ---------------------------------------------------------------------------
__device__ __forceinline__ unsigned f2tf(float x) {
    unsigned u;
    asm("cvt.rna.tf32.f32 %0, %1;" : "=r"(u) : "f"(x));
    return u;
}

__device__ __forceinline__ int ld_acq(const int* a) {
    int v;
    asm volatile("ld.acquire.gpu.s32 %0, [%1];" : "=r"(v) : "l"(a) : "memory");
    return v;
}

__device__ __forceinline__ void red_release(int* a) {
    asm volatile("red.release.gpu.global.add.s32 [%0], 1;" :: "l"(a) : "memory");
}

__device__ __forceinline__ void wait_ge(const int* a, int tgt) {
    if (ld_acq(a) >= tgt) return;
    while (ld_acq(a) < tgt) __nanosleep(32);
}

__device__ __forceinline__ void prefetchL2(const void* p) {
    asm volatile("prefetch.global.L2 [%0];" :: "l"(p));
}

#define MMA_TF32(C, A, B)                                                     \
    asm volatile(                                                             \
        "mma.sync.aligned.m16n8k8.row.col.f32.tf32.tf32.f32 "                 \
        "{%0,%1,%2,%3}, {%4,%5,%6,%7}, {%8,%9}, {%0,%1,%2,%3};"               \
        : "+f"((C)[0]), "+f"((C)[1]), "+f"((C)[2]), "+f"((C)[3])              \
        : "r"((A).x), "r"((A).y), "r"((A).z), "r"((A).w),                     \
          "r"((B).x), "r"((B).y))

// Fragment index of element (row b in 0..127, col n in 0..1023), m16n8k8 A layout:
// uint index = ((k8*8 + mtile)*32 + lane)*4 + reg
__device__ __forceinline__ int frag_idx(int b, int n) {
    int kc = n & 7;
    int lane = (b & 7) * 4 + (kc & 3);
    int reg  = ((b >> 3) & 1) + ((kc >> 2) << 1);
    return ((((n >> 3) << 3) + (b >> 4)) * 32 + lane) * 4 + reg;
}

// ---------------------------------------------------------------------------
// Init: zero sync state, fill initial-state fragment buffers
// ---------------------------------------------------------------------------
__global__ void init_kernel(const float* __restrict__ h0in)
{
    int idx = blockIdx.x * blockDim.x + threadIdx.x;
    if (idx < 16) { g_cntA[idx] = 0; g_cntB[idx] = 0; }
    if (idx == 16) { g_barA = 0; g_barB = 0; }
    for (int e = idx; e < 2 * BH; e += gridDim.x * blockDim.x) {
        int which = e >> 17;
        int r = e & (BH - 1);
        int b = r >> 10, n = r & 1023;
        unsigned v = f2tf(h0in[which * Hd + n]);
        if (which == 0) g_h0frag[1][frag_idx(b, n)] = v;
        else            g_h1frag[1][frag_idx(b, n)] = v;
    }
}

// ---------------------------------------------------------------------------
// xprep: x [B,T,H] fp32 -> per-token fragment tf32 in g_xfrag (one-shot).
// ---------------------------------------------------------------------------
__global__ void xprep_kernel(const float* __restrict__ x)
{
    const int total = BT * Hd / 4;
    for (int e = blockIdx.x * blockDim.x + threadIdx.x; e < total;
         e += gridDim.x * blockDim.x) {
        int n  = (e & 255) * 4;
        int bt = e >> 8;
        int b  = bt >> 8;
        int t  = bt & 255;
        float4 v = *(const float4*)(x + (size_t)e * 4);
        unsigned* dst = g_xfrag + (size_t)t * BH;
        dst[frag_idx(b, n + 0)] = f2tf(v.x);
        dst[frag_idx(b, n + 1)] = f2tf(v.y);
        dst[frag_idx(b, n + 2)] = f2tf(v.z);
        dst[frag_idx(b, n + 3)] = f2tf(v.w);
    }
}

// ---------------------------------------------------------------------------
// Persistent kernel (R7 control flow + kg-split warp layout).
// Grid = 128 blocks x 512 threads, 1 block/SM.
//   part = bid/32: 0=Gh0 [A], 1=Gi1 [B], 2=Gh1 [B], 3=Gp=x_p@Wi0 [A]
//   sub = bid%32: tile = sub>>1 (N-tile of 64), kh = sub&1 (K-half of 512).
// Warp layout: wm = wid&7 (M-tile of 16), kg = wid>>3 (K-group of 256).
//   Each warp: M=16, N=64 (8 ntiles), K=256 — A-fragment addresses are
//   DISJOINT across all 16 warps (block reads its A slice exactly once).
//   kg=1 accumulators folded into kg=0 via one 32KB smem exchange.
// Sync (as R7, fences replaced by release arrivals):
//   A-group (parts 0,3): entry barA>=64p; combine cntA>=4(p+1);
//     WAR barB>=64(p-1) before epilogue; epilogue -> h0frag[p&1]; arrive barA.
//   B-group (parts 1,2): entry barA>=64p, barB>=64(p-1); combine cntB>=4p;
//     epilogue -> out, h1frag[(p-1)&1]; arrive barB.
// ---------------------------------------------------------------------------
extern __shared__ unsigned smemAll[];   // Bw: 32768 uints (128KB) + red: 8KB*... (32KB)

__global__ __launch_bounds__(512, 1) void persistent_kernel(
    const float* __restrict__ Wi, const float* __restrict__ bi,
    const float* __restrict__ Wh, const float* __restrict__ bh,
    float* __restrict__ out)
{
    const int part = blockIdx.x >> 5;     // 0..3
    const int sub  = blockIdx.x & 31;
    const int tile = sub >> 1;
    const int kh   = sub & 1;
    const bool isA = (part == 0 || part == 3);

    const int tid  = threadIdx.x;
    const int lane = tid & 31;
    const int wid  = tid >> 5;
    const int wm   = wid & 7;             // M-tile (16 rows)
    const int kg   = wid >> 3;            // K-group (32 k8-steps of this K-half)
    const int n0   = tile * 64;
    const int kstart = kh * 512;

    unsigned* Bw = smemAll;                       // [64 k8][8 nt][32 lane][2 reg]
    float4*  red = (float4*)(smemAll + 32768);    // [8 wm][8 q][32 lane]

    const float* wbase = (part == 0) ? Wh
                       : (part == 1) ? Wi + (size_t)Hd * Hd
                       : (part == 2) ? Wh + (size_t)Hd * Hd
                                     : Wi;

    // ---- one-time weight preload into fragment-ready smem ----
#pragma unroll 4
    for (int i = 0; i < 16; i++) {
        int idx = tid + 512 * i;
        int krow = idx >> 4;
        int c4   = idx & 15;
        float4 w = *(const float4*)(wbase + (size_t)(kstart + krow) * Hd + n0 + c4 * 4);
        int k8 = krow >> 3, kk = krow & 7, ntile = c4 >> 1;
        int base = ((k8 * 8 + ntile) * 32 + (c4 & 1) * 16 + (kk & 3)) * 2 + (kk >> 2);
        Bw[base +  0] = f2tf(w.x);
        Bw[base +  8] = f2tf(w.y);
        Bw[base + 16] = f2tf(w.z);
        Bw[base + 24] = f2tf(w.w);
    }
    __syncthreads();

    float* mp = g_part[(part == 3) ? (6 + kh) : (part * 2 + kh)];

    const int pstart = isA ? 0 : 1;
    const int pend   = isA ? Tt - 1 : Tt;

    for (int p = pstart; p <= pend; ++p) {
        // ---- entry flow wait ----
        if (tid == 0) {
            if (isA) {
                if (p > 0) wait_ge(&g_barA, 64 * p);
            } else {
                wait_ge(&g_barA, 64 * p);
                if (p > 1) wait_ge(&g_barB, 64 * (p - 1));
            }
        }
        __syncthreads();

        const unsigned* afrag =
            (part == 0) ? g_h0frag[(p - 1) & 1] :
            (part == 1) ? g_h0frag[(p - 1) & 1] :
            (part == 2) ? g_h1frag[p & 1]
                        : g_xfrag + (size_t)p * BH;
        // this warp's disjoint A stream: k8 range [kh*64 + kg*32, +32), m-tile wm
        const uint4* abase = ((const uint4*)afrag)
                             + ((size_t)(kh * 64 + kg * 32) * 8 + wm) * 32 + lane;

        float c[8][4];
#pragma unroll
        for (int nt = 0; nt < 8; nt++)
#pragma unroll
            for (int r = 0; r < 4; r++) c[nt][r] = 0.0f;

        uint4 pa[8];
#pragma unroll
        for (int i = 0; i < 8; i++)
            pa[i] = __ldcg(abase + i * 256);

#pragma unroll 8
        for (int k8l = 0; k8l < 32; k8l++) {
            uint4 a = pa[k8l & 7];
            if (k8l < 24)
                pa[k8l & 7] = __ldcg(abase + (k8l + 8) * 256);
            const int k8 = kg * 32 + k8l;
#pragma unroll
            for (int nt = 0; nt < 8; nt++) {
                uint2 bfr = *(const uint2*)&Bw[(((k8 << 3) + nt) * 32 + lane) * 2];
                MMA_TF32(c[nt], a, bfr);
            }
        }

        // ---- kg combine: kg1 -> smem, kg0 adds ----
        if (kg == 1) {
#pragma unroll
            for (int q = 0; q < 8; q++)
                red[(wm * 8 + q) * 32 + lane] =
                    make_float4(c[q][0], c[q][1], c[q][2], c[q][3]);
        }
        __syncthreads();
        if (kg == 0) {
#pragma unroll
            for (int q = 0; q < 8; q++) {
                float4 r = red[(wm * 8 + q) * 32 + lane];
                c[q][0] += r.x; c[q][1] += r.y; c[q][2] += r.z; c[q][3] += r.w;
            }
            // partial -> global (rows wm*16..+16, all 64 cols)
            const int gq = lane >> 2, tq = lane & 3;
#pragma unroll
            for (int nt = 0; nt < 8; nt++) {
                int row = wm * 16 + gq;
                int col = n0 + nt * 8 + 2 * tq;
                *(float2*)&mp[(size_t)row * Hd + col] = make_float2(c[nt][0], c[nt][1]);
                *(float2*)&mp[(size_t)(row + 8) * Hd + col] = make_float2(c[nt][2], c[nt][3]);
            }
        }

        // full L2 prefetch of next-phase x slice (part 3): 2048 lines of 128B
        if (part == 3 && p + 1 < Tt) {
            const char* nx = (const char*)(g_xfrag
                              + (size_t)(p + 1) * BH + (size_t)kh * 65536);
#pragma unroll
            for (int i = 0; i < 4; i++)
                prefetchL2(nx + ((size_t)tid + i * 512) * 128);
        }

        // ---- tile combine sync (4 contributors) + A's WAR wait ----
        __syncthreads();
        if (tid == 0) {
            int* cnt = isA ? &g_cntA[tile] : &g_cntB[tile];
            red_release(cnt);
            const int tgt = isA ? 4 * (p + 1) : 4 * p;
            wait_ge(cnt, tgt);
            if (isA && p >= 2)
                wait_ge(&g_barB, 64 * (p - 1));    // WAR on h0frag parity buffer
        }
        __syncthreads();

        // ---- distributed epilogue: 4 blocks/tile, each 32 rows x 64 cols ----
        const int chunk = isA ? ((part == 0 ? 0 : 2) + kh)
                              : ((part - 1) * 2 + kh);
        const int row = chunk * 32 + (tid >> 4);
        const int n   = n0 + (tid & 15) * 4;
        if (isA) {
            unsigned* dstf = g_h0frag[p & 1];
            float4 a = __ldcg((const float4*)&g_part[0][(size_t)row * Hd + n]);
            float4 b = __ldcg((const float4*)&g_part[1][(size_t)row * Hd + n]);
            float4 q = __ldcg((const float4*)&g_part[6][(size_t)row * Hd + n]);
            float4 s = __ldcg((const float4*)&g_part[7][(size_t)row * Hd + n]);
            float4 b1 = *(const float4*)&bi[n];
            float4 b2 = *(const float4*)&bh[n];
            float r0 = tanhf(a.x + b.x + q.x + s.x + b1.x + b2.x);
            float r1 = tanhf(a.y + b.y + q.y + s.y + b1.y + b2.y);
            float r2 = tanhf(a.z + b.z + q.z + s.z + b1.z + b2.z);
            float r3 = tanhf(a.w + b.w + q.w + s.w + b1.w + b2.w);
            if (p == Tt - 1)
                *(float4*)&g_h0f[(size_t)row * Hd + n] = make_float4(r0, r1, r2, r3);
            dstf[frag_idx(row, n + 0)] = f2tf(r0);
            dstf[frag_idx(row, n + 1)] = f2tf(r1);
            dstf[frag_idx(row, n + 2)] = f2tf(r2);
            dstf[frag_idx(row, n + 3)] = f2tf(r3);
        } else {
            const int tt = p - 1;
            unsigned* dstf = g_h1frag[(p - 1) & 1];
            float4 s2 = __ldcg((const float4*)&g_part[2][(size_t)row * Hd + n]);
            float4 s3 = __ldcg((const float4*)&g_part[3][(size_t)row * Hd + n]);
            float4 s4 = __ldcg((const float4*)&g_part[4][(size_t)row * Hd + n]);
            float4 s5 = __ldcg((const float4*)&g_part[5][(size_t)row * Hd + n]);
            float4 b1 = *(const float4*)&bi[Hd + n];
            float4 b2 = *(const float4*)&bh[Hd + n];
            float r0 = tanhf(s2.x + s3.x + s4.x + s5.x + b1.x + b2.x);
            float r1 = tanhf(s2.y + s3.y + s4.y + s5.y + b1.y + b2.y);
            float r2 = tanhf(s2.z + s3.z + s4.z + s5.z + b1.z + b2.z);
            float r3 = tanhf(s2.w + s3.w + s4.w + s5.w + b1.w + b2.w);
            *(float4*)&out[((size_t)row * Tt + tt) * Hd + n] =
                make_float4(r0, r1, r2, r3);
            dstf[frag_idx(row, n + 0)] = f2tf(r0);
            dstf[frag_idx(row, n + 1)] = f2tf(r1);
            dstf[frag_idx(row, n + 2)] = f2tf(r2);
            dstf[frag_idx(row, n + 3)] = f2tf(r3);
        }

        // ---- group phase arrival (release publishes this block's writes) ----
        __syncthreads();
        if (tid == 0) red_release(isA ? &g_barA : &g_barB);
    }
}

// ---------------------------------------------------------------------------
// Finalize: h_n[b][0] = h0_{T-1}, h_n[b][1] = h1_{T-1} (= out[:,T-1,:])
// ---------------------------------------------------------------------------
__global__ void finalize_kernel(float* __restrict__ out)
{
    int idx = blockIdx.x * blockDim.x + threadIdx.x;
    if (idx >= BH) return;
    int b = idx / Hd, h = idx % Hd;
    float* hn = out + (size_t)BT * Hd;
    hn[((size_t)b * 2 + 0) * Hd + h] = g_h0f[(size_t)b * Hd + h];
    hn[((size_t)b * 2 + 1) * Hd + h] = out[((size_t)b * Tt + (Tt - 1)) * Hd + h];
}

// ---------------------------------------------------------------------------
extern "C" void kernel_launch(void* const* d_in, const int* in_sizes, int n_in,
                              void* d_out, int out_size)
{
    const float* x    = (const float*)d_in[0];   // [B,T,H]
    const float* h0in = (const float*)d_in[1];   // [1,L,H]
    const float* Wi   = (const float*)d_in[2];   // [L,H,H]
    const float* bi   = (const float*)d_in[3];   // [L,H]
    const float* Wh   = (const float*)d_in[4];   // [L,H,H]
    const float* bh   = (const float*)d_in[5];   // [L,H]
    float* out = (float*)d_out;                  // [B,T,H] then [B,L,H]

    init_kernel<<<256, 256>>>(h0in);
    xprep_kernel<<<8192, 256>>>(x);

    cudaFuncSetAttribute(persistent_kernel,
                         cudaFuncAttributeMaxDynamicSharedMemorySize, 163840);
    persistent_kernel<<<128, 512, 163840>>>(Wi, bi, Wh, bh, out);

    finalize_kernel<<<(BH + 255) / 256, 256>>>(out);
}